// round 1
// baseline (speedup 1.0000x reference)
#include <cuda_runtime.h>

#define N_NODES 100000
#define N_EDGES 1000000
#define D 64
#define DV4 16   // D/4 float4 per row

// ---------------- scratch (static device globals; no allocation) ----------------
__device__ float g_agg[N_NODES * D];     // aggregation buffer
__device__ float g_h[N_NODES * D];       // hidden layer output (ping)
__device__ float g_out_norm[N_NODES];
__device__ float g_in_norm[N_NODES];
__device__ int   g_deg_out[N_NODES];
__device__ int   g_deg_in[N_NODES];

// ---------------- degree / norm ----------------
__global__ void zero_deg_kernel() {
    int i = blockIdx.x * blockDim.x + threadIdx.x;
    if (i < N_NODES) { g_deg_out[i] = 0; g_deg_in[i] = 0; }
}

__global__ void count_kernel(const int* __restrict__ src, const int* __restrict__ dst) {
    int e = blockIdx.x * blockDim.x + threadIdx.x;
    if (e < N_EDGES) {
        atomicAdd(&g_deg_out[src[e]], 1);
        atomicAdd(&g_deg_in[dst[e]], 1);
    }
}

__global__ void norm_kernel() {
    int i = blockIdx.x * blockDim.x + threadIdx.x;
    if (i < N_NODES) {
        int dout = g_deg_out[i]; if (dout < 1) dout = 1;
        int din  = g_deg_in[i];  if (din  < 1) din  = 1;
        g_out_norm[i] = rsqrtf((float)dout);
        g_in_norm[i]  = rsqrtf((float)din);
    }
}

// ---------------- zero the aggregation buffer ----------------
__global__ void zero_agg_kernel() {
    int i = blockIdx.x * blockDim.x + threadIdx.x;
    if (i < N_NODES * DV4)
        reinterpret_cast<float4*>(g_agg)[i] = make_float4(0.f, 0.f, 0.f, 0.f);
}

// ---------------- edge scatter: agg[dst] += x[src] * out_norm[src] ----------------
// 16 threads per edge, each handling one float4 (16B) => 256B/edge fully coalesced.
// Vector red.global.add.v4.f32 cuts atomic op count 4x vs scalar atomicAdd.
__global__ void scatter_kernel(const float4* __restrict__ xin,
                               const int* __restrict__ src,
                               const int* __restrict__ dst) {
    const float4* in = xin ? xin : reinterpret_cast<const float4*>(g_h);
    __shared__ int   s_src[16];
    __shared__ int   s_dst[16];
    __shared__ float s_scale[16];

    int tid = threadIdx.x;
    int ebase = blockIdx.x * 16;
    if (tid < 16) {
        int s = src[ebase + tid];
        s_src[tid] = s;
        s_dst[tid] = dst[ebase + tid];
        s_scale[tid] = g_out_norm[s];
    }
    __syncthreads();

    int el = tid >> 4;
    int c  = tid & 15;
    int srow = s_src[el];
    int drow = s_dst[el];
    float sc = s_scale[el];

    float4 v = __ldg(&in[srow * DV4 + c]);
    v.x *= sc; v.y *= sc; v.z *= sc; v.w *= sc;

    float* addr = reinterpret_cast<float*>(
        reinterpret_cast<float4*>(g_agg) + drow * DV4 + c);
    asm volatile("red.global.add.v4.f32 [%0], {%1,%2,%3,%4};"
                 :: "l"(addr), "f"(v.x), "f"(v.y), "f"(v.z), "f"(v.w)
                 : "memory");
}

// ---------------- per-node GEMM: out = relu?( in_norm[row]*(agg@W) + b ) ----------
// W (64x64, 16KB) staged in shared; all threads read the same sW element per FMA
// (broadcast, conflict-free). One row per thread, 64 fp32 accumulators.
__global__ void __launch_bounds__(128) gemm_kernel(
        const float* __restrict__ W, const float* __restrict__ b,
        float* __restrict__ outp, int relu) {
    __shared__ float sW[D * D];
    int tid = threadIdx.x;
    for (int i = tid; i < D * D; i += blockDim.x) sW[i] = W[i];
    __syncthreads();

    int row = blockIdx.x * blockDim.x + tid;
    if (row >= N_NODES) return;

    float acc[D];
#pragma unroll
    for (int j = 0; j < D; j++) acc[j] = 0.f;

    const float4* arow = reinterpret_cast<const float4*>(g_agg) + row * DV4;
#pragma unroll
    for (int kk = 0; kk < DV4; kk++) {
        float4 a4 = __ldg(&arow[kk]);
        float av[4] = {a4.x, a4.y, a4.z, a4.w};
#pragma unroll
        for (int q = 0; q < 4; q++) {
            float a = av[q];
            const float* wrow = &sW[(kk * 4 + q) * D];
#pragma unroll
            for (int j = 0; j < D; j++)
                acc[j] = fmaf(a, wrow[j], acc[j]);
        }
    }

    float nrm = g_in_norm[row];
    float* out = outp ? outp : g_h;
    float4* orow = reinterpret_cast<float4*>(out + row * D);
#pragma unroll
    for (int j4 = 0; j4 < DV4; j4++) {
        float o[4];
#pragma unroll
        for (int q = 0; q < 4; q++) {
            float v = fmaf(nrm, acc[j4 * 4 + q], __ldg(&b[j4 * 4 + q]));
            if (relu) v = fmaxf(v, 0.f);
            o[q] = v;
        }
        orow[j4] = make_float4(o[0], o[1], o[2], o[3]);
    }
}

// ---------------- launch ----------------
extern "C" void kernel_launch(void* const* d_in, const int* in_sizes, int n_in,
                              void* d_out, int out_size) {
    const float* x   = (const float*)d_in[0];
    const int*   src = (const int*)d_in[1];
    const int*   dst = (const int*)d_in[2];
    const float* W1  = (const float*)d_in[3];
    const float* b1  = (const float*)d_in[4];
    const float* W2  = (const float*)d_in[5];
    const float* b2  = (const float*)d_in[6];
    const float* W3  = (const float*)d_in[7];
    const float* b3  = (const float*)d_in[8];
    float* out = (float*)d_out;

    const int TB = 256;
    // degrees + norms
    zero_deg_kernel<<<(N_NODES + TB - 1) / TB, TB>>>();
    count_kernel<<<(N_EDGES + TB - 1) / TB, TB>>>(src, dst);
    norm_kernel<<<(N_NODES + TB - 1) / TB, TB>>>();

    const int ZG = (N_NODES * DV4 + TB - 1) / TB;
    const int SG = N_EDGES / 16;           // 16 edges per 256-thread block
    const int GG = (N_NODES + 127) / 128;

    // layer 1: x -> g_agg -> g_h (relu)
    zero_agg_kernel<<<ZG, TB>>>();
    scatter_kernel<<<SG, TB>>>(reinterpret_cast<const float4*>(x), src, dst);
    gemm_kernel<<<GG, 128>>>(W1, b1, nullptr, 1);

    // layer 2: g_h -> g_agg -> g_h (relu)
    zero_agg_kernel<<<ZG, TB>>>();
    scatter_kernel<<<SG, TB>>>(nullptr, src, dst);
    gemm_kernel<<<GG, 128>>>(W2, b2, nullptr, 1);

    // layer 3: g_h -> g_agg -> d_out (no relu)
    zero_agg_kernel<<<ZG, TB>>>();
    scatter_kernel<<<SG, TB>>>(nullptr, src, dst);
    gemm_kernel<<<GG, 128>>>(W3, b3, out, 0);
}

// round 2
// speedup vs baseline: 1.4846x; 1.4846x over previous
#include <cuda_runtime.h>

#define NN 100000
#define NE 1000000
#define D  64
#define HS 68              // smem h-row stride (floats), 16B-aligned, conflict-shifted
#define SCAN_BS 1024
#define NBLK 98            // ceil(NN/1024)

// ---------------- static scratch ----------------
__device__ float g_bufA[NN * D];      // xs (scaled x), later layer-2 output
__device__ float g_bufB[NN * D];      // layer-1 output
__device__ float g_out_norm[NN];
__device__ float g_in_norm[NN];
__device__ int   g_deg_out[NN];
__device__ int   g_deg_in[NN];
__device__ int   g_row_start[NN];
__device__ int   g_fill[NN];
__device__ int   g_src_sorted[NE];
__device__ int   g_bsum[NBLK];
__device__ int   g_boff[NBLK];

// ---------------- f32x2 helpers ----------------
__device__ __forceinline__ unsigned long long pk2(float lo, float hi) {
    unsigned long long r;
    asm("mov.b64 %0, {%1,%2};" : "=l"(r) : "f"(lo), "f"(hi));
    return r;
}
__device__ __forceinline__ void fma2(unsigned long long& d,
                                     unsigned long long a, unsigned long long b) {
    asm("fma.rn.f32x2 %0, %1, %2, %0;" : "+l"(d) : "l"(a), "l"(b));
}
__device__ __forceinline__ float2 upk2(unsigned long long v) {
    float2 f;
    asm("mov.b64 {%0,%1}, %2;" : "=f"(f.x), "=f"(f.y) : "l"(v));
    return f;
}

// ---------------- setup kernels ----------------
__global__ void zero_deg_kernel() {
    int i = blockIdx.x * blockDim.x + threadIdx.x;
    if (i < NN) { g_deg_out[i] = 0; g_deg_in[i] = 0; }
}

__global__ void count_kernel(const int* __restrict__ src, const int* __restrict__ dst) {
    int e = blockIdx.x * blockDim.x + threadIdx.x;
    if (e < NE) {
        atomicAdd(&g_deg_out[src[e]], 1);
        atomicAdd(&g_deg_in[dst[e]], 1);
    }
}

__global__ void norm_kernel() {
    int i = blockIdx.x * blockDim.x + threadIdx.x;
    if (i < NN) {
        int dout = g_deg_out[i]; if (dout < 1) dout = 1;
        int din  = g_deg_in[i];  if (din  < 1) din  = 1;
        g_out_norm[i] = rsqrtf((float)dout);
        g_in_norm[i]  = rsqrtf((float)din);
    }
}

// block-level exclusive scan of deg_in
__global__ void scan1_kernel() {
    __shared__ int sh[SCAN_BS];
    int t = threadIdx.x;
    int i = blockIdx.x * SCAN_BS + t;
    int v = (i < NN) ? g_deg_in[i] : 0;
    sh[t] = v;
    __syncthreads();
#pragma unroll
    for (int off = 1; off < SCAN_BS; off <<= 1) {
        int xv = (t >= off) ? sh[t - off] : 0;
        __syncthreads();
        sh[t] += xv;
        __syncthreads();
    }
    if (i < NN) g_row_start[i] = sh[t] - v;   // exclusive within block
    if (t == SCAN_BS - 1) g_bsum[blockIdx.x] = sh[t];
}

__global__ void scan2_kernel() {
    if (threadIdx.x == 0) {
        int acc = 0;
        for (int b = 0; b < NBLK; b++) { g_boff[b] = acc; acc += g_bsum[b]; }
    }
}

__global__ void scan3_kernel() {
    int i = blockIdx.x * blockDim.x + threadIdx.x;
    if (i < NN) {
        int rs = g_row_start[i] + g_boff[i >> 10];
        g_row_start[i] = rs;
        g_fill[i] = rs;
    }
}

__global__ void fill_kernel(const int* __restrict__ src, const int* __restrict__ dst) {
    int e = blockIdx.x * blockDim.x + threadIdx.x;
    if (e < NE) {
        int p = atomicAdd(&g_fill[dst[e]], 1);
        g_src_sorted[p] = src[e];
    }
}

// xs = x * out_norm[row]  (into bufA)
__global__ void prescale_kernel(const float4* __restrict__ x) {
    int i = blockIdx.x * blockDim.x + threadIdx.x;
    if (i < NN * (D / 4)) {
        float s = g_out_norm[i >> 4];
        float4 v = __ldg(&x[i]);
        v.x *= s; v.y *= s; v.z *= s; v.w *= s;
        reinterpret_cast<float4*>(g_bufA)[i] = v;
    }
}

// ---------------- fused gather + GEMM layer ----------------
// block = 256 threads, 16 nodes/block.
// Phase 1: 16-lane groups gather-sum in-edges (CSR), scale by in_norm, stash row in smem.
// Phase 2: warps 0-1 each GEMM 8 nodes against W (smem), FFMA2, epilogue bias/relu/out_norm.
__global__ void __launch_bounds__(256) layer_kernel(
        int in_is_B, float* __restrict__ out_ext, int out_is_B,
        const float* __restrict__ W, const float* __restrict__ b,
        int relu, int scale_out) {
    __shared__ float sW[D * D];     // 16KB
    __shared__ float sh[16 * HS];   // node rows
    __shared__ float sb[D];

    int tid = threadIdx.x;
    for (int i = tid; i < D * D; i += 256) sW[i] = W[i];
    if (tid < D) sb[tid] = b[tid];

    const float* in = in_is_B ? g_bufB : g_bufA;
    float* outp = out_ext ? out_ext : (out_is_B ? g_bufB : g_bufA);

    // ---- phase 1: aggregation ----
    int g = tid >> 4, c = tid & 15;
    int node = blockIdx.x * 16 + g;
    float4 acc = make_float4(0.f, 0.f, 0.f, 0.f);
    if (node < NN) {
        const float4* inp = reinterpret_cast<const float4*>(in);
        int e = g_row_start[node];
        int eend = e + g_deg_in[node];
        for (; e + 1 < eend; e += 2) {
            int sA = g_src_sorted[e];
            int sB = g_src_sorted[e + 1];
            float4 a = __ldg(&inp[sA * 16 + c]);
            float4 bb = __ldg(&inp[sB * 16 + c]);
            acc.x += a.x + bb.x; acc.y += a.y + bb.y;
            acc.z += a.z + bb.z; acc.w += a.w + bb.w;
        }
        if (e < eend) {
            int sA = g_src_sorted[e];
            float4 a = __ldg(&inp[sA * 16 + c]);
            acc.x += a.x; acc.y += a.y; acc.z += a.z; acc.w += a.w;
        }
        float nrm = g_in_norm[node];
        acc.x *= nrm; acc.y *= nrm; acc.z *= nrm; acc.w *= nrm;
    }
    *reinterpret_cast<float4*>(&sh[g * HS + c * 4]) = acc;
    __syncthreads();

    // ---- phase 2: GEMM (warps 0,1; 8 nodes each) ----
    int w = tid >> 5;
    if (w < 2) {
        int lane = tid & 31;
        int r0 = lane >> 4;       // 0/1
        int c2 = lane & 15;       // output col quad
        unsigned long long acc01[4], acc23[4];
#pragma unroll
        for (int m = 0; m < 4; m++) { acc01[m] = 0ull; acc23[m] = 0ull; }

#pragma unroll
        for (int kb = 0; kb < 16; kb++) {
            float4 a4[4];
#pragma unroll
            for (int m = 0; m < 4; m++)
                a4[m] = *reinterpret_cast<const float4*>(
                    &sh[(w * 8 + r0 + 2 * m) * HS + kb * 4]);
#pragma unroll
            for (int q = 0; q < 4; q++) {
                int k = kb * 4 + q;
                unsigned long long w01 =
                    *reinterpret_cast<const unsigned long long*>(&sW[k * D + c2 * 4]);
                unsigned long long w23 =
                    *reinterpret_cast<const unsigned long long*>(&sW[k * D + c2 * 4 + 2]);
#pragma unroll
                for (int m = 0; m < 4; m++) {
                    float a = (q == 0) ? a4[m].x : (q == 1) ? a4[m].y
                             : (q == 2) ? a4[m].z : a4[m].w;
                    unsigned long long aa = pk2(a, a);
                    fma2(acc01[m], aa, w01);
                    fma2(acc23[m], aa, w23);
                }
            }
        }
        // epilogue
        float b0 = sb[c2 * 4 + 0], b1 = sb[c2 * 4 + 1];
        float b2 = sb[c2 * 4 + 2], b3 = sb[c2 * 4 + 3];
#pragma unroll
        for (int m = 0; m < 4; m++) {
            int nd = blockIdx.x * 16 + w * 8 + r0 + 2 * m;
            if (nd < NN) {
                float2 v01 = upk2(acc01[m]);
                float2 v23 = upk2(acc23[m]);
                float o0 = v01.x + b0, o1 = v01.y + b1;
                float o2 = v23.x + b2, o3 = v23.y + b3;
                if (relu) {
                    o0 = fmaxf(o0, 0.f); o1 = fmaxf(o1, 0.f);
                    o2 = fmaxf(o2, 0.f); o3 = fmaxf(o3, 0.f);
                }
                if (scale_out) {
                    float on = g_out_norm[nd];
                    o0 *= on; o1 *= on; o2 *= on; o3 *= on;
                }
                reinterpret_cast<float4*>(outp)[nd * 16 + c2] =
                    make_float4(o0, o1, o2, o3);
            }
        }
    }
}

// ---------------- launch ----------------
extern "C" void kernel_launch(void* const* d_in, const int* in_sizes, int n_in,
                              void* d_out, int out_size) {
    const float* x   = (const float*)d_in[0];
    const int*   src = (const int*)d_in[1];
    const int*   dst = (const int*)d_in[2];
    const float* W1  = (const float*)d_in[3];
    const float* b1  = (const float*)d_in[4];
    const float* W2  = (const float*)d_in[5];
    const float* b2  = (const float*)d_in[6];
    const float* W3  = (const float*)d_in[7];
    const float* b3  = (const float*)d_in[8];
    float* out = (float*)d_out;

    const int TB = 256;
    const int GN = (NN + TB - 1) / TB;
    const int GE = (NE + TB - 1) / TB;

    zero_deg_kernel<<<GN, TB>>>();
    count_kernel<<<GE, TB>>>(src, dst);
    norm_kernel<<<GN, TB>>>();
    scan1_kernel<<<NBLK, SCAN_BS>>>();
    scan2_kernel<<<1, 32>>>();
    scan3_kernel<<<GN, TB>>>();
    fill_kernel<<<GE, TB>>>(src, dst);
    prescale_kernel<<<(NN * 16 + TB - 1) / TB, TB>>>(
        reinterpret_cast<const float4*>(x));

    const int GL = (NN + 15) / 16;
    // layer 1: bufA(xs) -> bufB, relu, scale by out_norm for next gather
    layer_kernel<<<GL, 256>>>(0, nullptr, 1, W1, b1, 1, 1);
    // layer 2: bufB -> bufA, relu, scale by out_norm
    layer_kernel<<<GL, 256>>>(1, nullptr, 0, W2, b2, 1, 1);
    // layer 3: bufA -> d_out, no relu, no scale
    layer_kernel<<<GL, 256>>>(0, out, 0, W3, b3, 0, 0);
}